// round 8
// baseline (speedup 1.0000x reference)
#include <cuda_runtime.h>

// AdditiveAttention (Bahdanau): B=2, L=S=512, H=8, E=32, D=64   — single fused kernel
// score[b,h,l,s] = sum_e v_e*tanh(q+k) + mask[l,s] + klen[b,s];  out = softmax_s @ values
// tanh(x) = 1 - 2/(1+e^{2x});  e^{2(q+k)} = Eq*Ek, Eq/Ek = ex2(2*log2e * {q,k})
// inner loop per element: LDS + FFMA(t=Eq*Ek+1) + MUFU.RCP + FFMA   (1 MUFU/elem)

#define BB 2
#define LL 512
#define SS 512
#define HH 8
#define EE 32
#define DD 64
#define LT 8           // L-rows per CTA (one warp per row)
#define NT 256
#define SPAD 516       // Ek smem row stride (float4-align preserved, bank-rotating)
#define SCALE 2.8853900817779268f   /* 2*log2(e) */
#define L2E   1.4426950408889634f

__device__ __forceinline__ float ex2f(float x) {
    float y; asm("ex2.approx.f32 %0, %1;" : "=f"(y) : "f"(x)); return y;
}
__device__ __forceinline__ float rcpf(float x) {
    float y; asm("rcp.approx.f32 %0, %1;" : "=f"(y) : "f"(x)); return y;
}

struct SmemT {
    union {
        float ek[16 * SPAD];                 // one e-half of Ek = ex2(k*SCALE), [e][s] (33KB)
        struct {                             // overlaid once ek is dead:
            float probs[LT * SS];            // 16KB
            float part[2 * LT * DD];         // 4KB
            float rowsum[LT];
        } p2;
    } u;
    float eqrow[LT * EE];                    // Eq for this CTA's 8 rows
    float vm2[EE];                           // -2*v_e
    float klen[SS];
};

__global__ void __launch_bounds__(NT, 4)
addattn_main(const float* __restrict__ q, const float* __restrict__ k,
             const float* __restrict__ vals, const float* __restrict__ vvec,
             const float* __restrict__ amask, const float* __restrict__ klen_g,
             float* __restrict__ out)
{
    __shared__ SmemT sm;

    const int tid  = threadIdx.x;
    const int wid  = tid >> 5;      // warp = L-row (0..7)
    const int lane = tid & 31;
    const int bid  = blockIdx.x;    // grid = 2*8*64 = 1024
    const int lt   = bid & 63;
    const int h    = (bid >> 6) & 7;
    const int b    = bid >> 9;
    const int l0   = lt * LT;

    const float* kbase = k + ((size_t)b * SS * HH + h) * EE;   // + s*HH*EE + e

    // ---- stage: Eq rows (with ex2), vm2, klen, Ek half-0 (ex2 on the fly) ----
    {
        int r = tid >> 5, e = tid & 31;   // 256 threads = 8 rows x 32 e
        float qv = q[(((size_t)(b * LL + l0 + r)) * HH + h) * EE + e];
        sm.eqrow[tid] = ex2f(qv * SCALE);
    }
    if (tid < EE) sm.vm2[tid] = -2.0f * vvec[tid];
    for (int s = tid; s < SS; s += NT) sm.klen[s] = klen_g[b * SS + s];

#pragma unroll
    for (int i = tid; i < 16 * SS; i += NT) {     // half-0: e in [0,16)
        int s = i >> 4, e = i & 15;
        float kv = kbase[(size_t)s * (HH * EE) + e];
        sm.u.ek[e * SPAD + s] = ex2f(kv * SCALE);
    }
    __syncthreads();

    float vsum = 0.f;
#pragma unroll
    for (int e = 0; e < EE; e++) vsum += sm.vm2[e];
    vsum *= -0.5f;                                 // sum_e v_e

    // ---- x init: score base + masks (overlaps phase-1) ----
    const float* amrow = amask + (size_t)(l0 + wid) * SS;
    float x[16];
#pragma unroll
    for (int j = 0; j < 16; j++) {
        int s = lane + 32 * j;
        x[j] = vsum + sm.klen[s] + amrow[s];
    }

    // ---- phase 1: scores in registers; j-blocked (8 live chains) ----
    for (int e = 0; e < 16; e++) {                 // e-half 0
        float eq = sm.eqrow[wid * EE + e];
        float vm = sm.vm2[e];
        const float* row = &sm.u.ek[e * SPAD + lane];
#pragma unroll
        for (int j0 = 0; j0 < 16; j0 += 8) {
            float t[8];
#pragma unroll
            for (int j = 0; j < 8; j++)
                t[j] = fmaf(eq, row[32 * (j0 + j)], 1.0f);
#pragma unroll
            for (int j = 0; j < 8; j++)
                x[j0 + j] = fmaf(vm, rcpf(t[j]), x[j0 + j]);
        }
    }
    __syncthreads();
#pragma unroll
    for (int i = tid; i < 16 * SS; i += NT) {     // stage half-1: e in [16,32)
        int s = i >> 4, e = i & 15;
        float kv = kbase[(size_t)s * (HH * EE) + 16 + e];
        sm.u.ek[e * SPAD + s] = ex2f(kv * SCALE);
    }
    __syncthreads();
    for (int e = 0; e < 16; e++) {                 // e-half 1
        float eq = sm.eqrow[wid * EE + 16 + e];
        float vm = sm.vm2[16 + e];
        const float* row = &sm.u.ek[e * SPAD + lane];
#pragma unroll
        for (int j0 = 0; j0 < 16; j0 += 8) {
            float t[8];
#pragma unroll
            for (int j = 0; j < 8; j++)
                t[j] = fmaf(eq, row[32 * (j0 + j)], 1.0f);
#pragma unroll
            for (int j = 0; j < 8; j++)
                x[j0 + j] = fmaf(vm, rcpf(t[j]), x[j0 + j]);
        }
    }
    __syncthreads();   // all warps done with sm.u.ek before probs overlay

    // ---- phase 2: in-warp softmax (unnormalized) ----
    float m = -1e30f;
#pragma unroll
    for (int j = 0; j < 16; j++) m = fmaxf(m, x[j]);
#pragma unroll
    for (int o = 16; o > 0; o >>= 1)
        m = fmaxf(m, __shfl_xor_sync(0xffffffffu, m, o));
    float ssum = 0.f;
#pragma unroll
    for (int j = 0; j < 16; j++) {
        float p = ex2f((x[j] - m) * L2E);
        ssum += p;
        sm.u.p2.probs[wid * SS + lane + 32 * j] = p;
    }
#pragma unroll
    for (int o = 16; o > 0; o >>= 1)
        ssum += __shfl_xor_sync(0xffffffffu, ssum, o);
    if (lane == 0) sm.u.p2.rowsum[wid] = ssum;
    __syncthreads();

    // ---- phase 3: A @ V (4 row-groups x 2 s-halves, 2 rows/warp) ----
    const int rg = wid & 3, sh = wid >> 2;
    const int r0 = rg * 2, r1 = r0 + 1;
    const int d0 = lane * 2;
    const float* vb = vals + ((size_t)(b * SS) * HH + h) * DD;
    float2 a0 = make_float2(0.f, 0.f), a1 = make_float2(0.f, 0.f);
    const int sbeg = sh * 256;
#pragma unroll 4
    for (int s = sbeg; s < sbeg + 256; s++) {
        float2 vv = *reinterpret_cast<const float2*>(vb + (size_t)s * (HH * DD) + d0);
        float p0 = sm.u.p2.probs[r0 * SS + s];
        float p1 = sm.u.p2.probs[r1 * SS + s];
        a0.x = fmaf(p0, vv.x, a0.x);  a0.y = fmaf(p0, vv.y, a0.y);
        a1.x = fmaf(p1, vv.x, a1.x);  a1.y = fmaf(p1, vv.y, a1.y);
    }
    *reinterpret_cast<float2*>(&sm.u.p2.part[(sh * LT + r0) * DD + d0]) = a0;
    *reinterpret_cast<float2*>(&sm.u.p2.part[(sh * LT + r1) * DD + d0]) = a1;
    __syncthreads();

    // ---- combine halves, normalize, store ----
    for (int i = tid; i < LT * DD; i += NT) {
        int row = i >> 6, d = i & 63;
        float val = (sm.u.p2.part[row * DD + d] + sm.u.p2.part[(LT + row) * DD + d])
                    * rcpf(sm.u.p2.rowsum[row]);
        out[(((size_t)(b * LL + l0 + row)) * HH + h) * DD + d] = val;
    }
}

extern "C" void kernel_launch(void* const* d_in, const int* in_sizes, int n_in,
                              void* d_out, int out_size)
{
    (void)in_sizes; (void)n_in; (void)out_size;
    const float* q     = (const float*)d_in[0];
    const float* k     = (const float*)d_in[1];
    const float* vals  = (const float*)d_in[2];
    const float* vvec  = (const float*)d_in[3];
    const float* amask = (const float*)d_in[4];
    const float* klen  = (const float*)d_in[5];

    addattn_main<<<BB * HH * (LL / LT), NT>>>(q, k, vals, vvec, amask, klen,
                                              (float*)d_out);
}

// round 10
// speedup vs baseline: 1.1667x; 1.1667x over previous
#include <cuda_runtime.h>

// AdditiveAttention (Bahdanau): B=2, L=S=512, H=8, E=32, D=64   — single fused kernel
// score[b,h,l,s] = sum_e v_e*tanh(q+k) + mask[l,s] + klen[b,s];  out = softmax_s @ values
// tanh(x) = 1 - 2/(1+e^{2x});  e^{2(q+k)} = Eq*Ek, Eq/Ek = ex2(2*log2e * {q,k})
// Pairwise combine (exact): wa/(1+xa)+wb/(1+xb) = (wa*tb+wb*ta)/(ta*tb)
// -> 1 MUFU.RCP per 2 elements

#define BB 2
#define LL 512
#define SS 512
#define HH 8
#define EE 32
#define DD 64
#define LT 8           // L-rows per CTA (one warp per row)
#define NT 256
#define SPAD 516       // Ek smem row stride (float4-align preserved, bank-rotating)
#define SCALE 2.8853900817779268f   /* 2*log2(e) */
#define L2E   1.4426950408889634f

__device__ __forceinline__ float ex2f(float x) {
    float y; asm("ex2.approx.f32 %0, %1;" : "=f"(y) : "f"(x)); return y;
}
__device__ __forceinline__ float rcpf(float x) {
    float y; asm("rcp.approx.f32 %0, %1;" : "=f"(y) : "f"(x)); return y;
}

struct SmemT {
    union {
        float ek[16 * SPAD];                 // one e-half of Ek = ex2(k*SCALE), [e][s] (33KB)
        struct {                             // overlaid once ek is dead:
            float probs[LT * SS];            // 16KB
            float part[2 * LT * DD];         // 4KB
            float rowsum[LT];
        } p2;
    } u;
    float eqrow[LT * EE];                    // Eq for this CTA's 8 rows
    float vm2[EE];                           // -2*v_e
    float klen[SS];
};

__global__ void __launch_bounds__(NT, 4)
addattn_main(const float* __restrict__ q, const float* __restrict__ k,
             const float* __restrict__ vals, const float* __restrict__ vvec,
             const float* __restrict__ amask, const float* __restrict__ klen_g,
             float* __restrict__ out)
{
    __shared__ SmemT sm;

    const int tid  = threadIdx.x;
    const int wid  = tid >> 5;      // warp = L-row (0..7)
    const int lane = tid & 31;
    const int bid  = blockIdx.x;    // grid = 2*8*64 = 1024
    const int lt   = bid & 63;
    const int h    = (bid >> 6) & 7;
    const int b    = bid >> 9;
    const int l0   = lt * LT;

    const float* kbase = k + ((size_t)b * SS * HH + h) * EE;   // + s*HH*EE + e

    // ---- stage: Eq rows (with ex2), vm2, klen, Ek half-0 (ex2 on the fly) ----
    {
        int r = tid >> 5, e = tid & 31;   // 256 threads = 8 rows x 32 e
        float qv = q[(((size_t)(b * LL + l0 + r)) * HH + h) * EE + e];
        sm.eqrow[tid] = ex2f(qv * SCALE);
    }
    if (tid < EE) sm.vm2[tid] = -2.0f * vvec[tid];
    for (int s = tid; s < SS; s += NT) sm.klen[s] = klen_g[b * SS + s];

#pragma unroll
    for (int i = tid; i < 16 * SS; i += NT) {     // half-0: e in [0,16)
        int s = i >> 4, e = i & 15;
        float kv = kbase[(size_t)s * (HH * EE) + e];
        sm.u.ek[e * SPAD + s] = ex2f(kv * SCALE);
    }
    __syncthreads();

    float vsum = 0.f;
#pragma unroll
    for (int e = 0; e < EE; e++) vsum += sm.vm2[e];
    vsum *= -0.5f;                                 // sum_e v_e

    // ---- x init: score base + masks ----
    const float* amrow = amask + (size_t)(l0 + wid) * SS;
    float x[16];
#pragma unroll
    for (int j = 0; j < 16; j++) {
        int s = lane + 32 * j;
        x[j] = vsum + sm.klen[s] + amrow[s];
    }

    // ---- phase 1, e-half 0: 8 e-pairs, 1 RCP per pair ----
    for (int ep = 0; ep < 8; ep++) {
        float eqa = sm.eqrow[wid * EE + 2 * ep];
        float eqb = sm.eqrow[wid * EE + 2 * ep + 1];
        float wa  = sm.vm2[2 * ep];
        float wb  = sm.vm2[2 * ep + 1];
        const float* rowa = &sm.u.ek[(2 * ep)     * SPAD + lane];
        const float* rowb = &sm.u.ek[(2 * ep + 1) * SPAD + lane];
#pragma unroll
        for (int j0 = 0; j0 < 16; j0 += 8) {
            float num[8], den[8];
#pragma unroll
            for (int j = 0; j < 8; j++) {
                float ta = fmaf(eqa, rowa[32 * (j0 + j)], 1.0f);
                float tb = fmaf(eqb, rowb[32 * (j0 + j)], 1.0f);
                den[j] = ta * tb;
                num[j] = fmaf(wb, ta, wa * tb);
            }
#pragma unroll
            for (int j = 0; j < 8; j++)
                x[j0 + j] = fmaf(num[j], rcpf(den[j]), x[j0 + j]);
        }
    }
    __syncthreads();
#pragma unroll
    for (int i = tid; i < 16 * SS; i += NT) {     // stage half-1: e in [16,32)
        int s = i >> 4, e = i & 15;
        float kv = kbase[(size_t)s * (HH * EE) + 16 + e];
        sm.u.ek[e * SPAD + s] = ex2f(kv * SCALE);
    }
    __syncthreads();
    // ---- phase 1, e-half 1 ----
    for (int ep = 0; ep < 8; ep++) {
        float eqa = sm.eqrow[wid * EE + 16 + 2 * ep];
        float eqb = sm.eqrow[wid * EE + 16 + 2 * ep + 1];
        float wa  = sm.vm2[16 + 2 * ep];
        float wb  = sm.vm2[16 + 2 * ep + 1];
        const float* rowa = &sm.u.ek[(2 * ep)     * SPAD + lane];
        const float* rowb = &sm.u.ek[(2 * ep + 1) * SPAD + lane];
#pragma unroll
        for (int j0 = 0; j0 < 16; j0 += 8) {
            float num[8], den[8];
#pragma unroll
            for (int j = 0; j < 8; j++) {
                float ta = fmaf(eqa, rowa[32 * (j0 + j)], 1.0f);
                float tb = fmaf(eqb, rowb[32 * (j0 + j)], 1.0f);
                den[j] = ta * tb;
                num[j] = fmaf(wb, ta, wa * tb);
            }
#pragma unroll
            for (int j = 0; j < 8; j++)
                x[j0 + j] = fmaf(num[j], rcpf(den[j]), x[j0 + j]);
        }
    }
    __syncthreads();   // all warps done with sm.u.ek before probs overlay

    // ---- phase 2: in-warp softmax (unnormalized) ----
    float m = -1e30f;
#pragma unroll
    for (int j = 0; j < 16; j++) m = fmaxf(m, x[j]);
#pragma unroll
    for (int o = 16; o > 0; o >>= 1)
        m = fmaxf(m, __shfl_xor_sync(0xffffffffu, m, o));
    float ssum = 0.f;
#pragma unroll
    for (int j = 0; j < 16; j++) {
        float p = ex2f((x[j] - m) * L2E);
        ssum += p;
        sm.u.p2.probs[wid * SS + lane + 32 * j] = p;
    }
#pragma unroll
    for (int o = 16; o > 0; o >>= 1)
        ssum += __shfl_xor_sync(0xffffffffu, ssum, o);
    if (lane == 0) sm.u.p2.rowsum[wid] = ssum;
    __syncthreads();

    // ---- phase 3: A @ V (4 row-groups x 2 s-halves, 2 rows/warp) ----
    const int rg = wid & 3, sh = wid >> 2;
    const int r0 = rg * 2, r1 = r0 + 1;
    const int d0 = lane * 2;
    const float* vb = vals + ((size_t)(b * SS) * HH + h) * DD;
    float2 a0 = make_float2(0.f, 0.f), a1 = make_float2(0.f, 0.f);
    const int sbeg = sh * 256;
#pragma unroll 4
    for (int s = sbeg; s < sbeg + 256; s++) {
        float2 vv = *reinterpret_cast<const float2*>(vb + (size_t)s * (HH * DD) + d0);
        float p0 = sm.u.p2.probs[r0 * SS + s];
        float p1 = sm.u.p2.probs[r1 * SS + s];
        a0.x = fmaf(p0, vv.x, a0.x);  a0.y = fmaf(p0, vv.y, a0.y);
        a1.x = fmaf(p1, vv.x, a1.x);  a1.y = fmaf(p1, vv.y, a1.y);
    }
    *reinterpret_cast<float2*>(&sm.u.p2.part[(sh * LT + r0) * DD + d0]) = a0;
    *reinterpret_cast<float2*>(&sm.u.p2.part[(sh * LT + r1) * DD + d0]) = a1;
    __syncthreads();

    // ---- combine halves, normalize, store ----
    for (int i = tid; i < LT * DD; i += NT) {
        int row = i >> 6, d = i & 63;
        float val = (sm.u.p2.part[row * DD + d] + sm.u.p2.part[(LT + row) * DD + d])
                    * rcpf(sm.u.p2.rowsum[row]);
        out[(((size_t)(b * LL + l0 + row)) * HH + h) * DD + d] = val;
    }
}

extern "C" void kernel_launch(void* const* d_in, const int* in_sizes, int n_in,
                              void* d_out, int out_size)
{
    (void)in_sizes; (void)n_in; (void)out_size;
    const float* q     = (const float*)d_in[0];
    const float* k     = (const float*)d_in[1];
    const float* vals  = (const float*)d_in[2];
    const float* vvec  = (const float*)d_in[3];
    const float* amask = (const float*)d_in[4];
    const float* klen  = (const float*)d_in[5];

    addattn_main<<<BB * HH * (LL / LT), NT>>>(q, k, vals, vvec, amask, klen,
                                              (float*)d_out);
}

// round 14
// speedup vs baseline: 1.3626x; 1.1679x over previous
#include <cuda_runtime.h>

// AdditiveAttention (Bahdanau): B=2, L=S=512, H=8, E=32, D=64
// score = sum_e v_e*tanh(q+k) + masks;  out = softmax_s @ values
// tanh(x) = 1 - 2/(1+e^{2x}); e^{2(q+k)} = Eq*Ek (prep kernel computes Ek)
// Pairwise combine (exact): wa/ta + wb/tb = (wa*tb+wb*ta)/(ta*tb), t = 1+Eq*Ek
// smem holds Ek in interleaved e-pairs -> one LDS.64 feeds both lanes of a pair.

#define BB 2
#define LL 512
#define SS 512
#define HH 8
#define EE 32
#define DD 64
#define LT 8            // L-rows per CTA (one warp per row in phase 1)
#define NT 256
#define SPAD2 514       // ek2 row stride in float2 units (16B-aligned rows)
#define SCALE 2.8853900817779268f   /* 2*log2(e) */
#define L2E   1.4426950408889634f

__device__ __forceinline__ float ex2f(float x) {
    float y; asm("ex2.approx.f32 %0, %1;" : "=f"(y) : "f"(x)); return y;
}
__device__ __forceinline__ float rcpf(float x) {
    float y; asm("rcp.approx.f32 %0, %1;" : "=f"(y) : "f"(x)); return y;
}

__device__ float g_Ek[BB * HH * EE * SS];   // [b][h][e][s] = ex2(k*SCALE)

__global__ void prep_ek(const float* __restrict__ k) {
    int i = blockIdx.x * blockDim.x + threadIdx.x;   // 262144
    int s = i & (SS - 1);
    int e = (i >> 9) & (EE - 1);
    int h = (i >> 14) & (HH - 1);
    int b = i >> 17;
    float kv = k[(((size_t)(b * SS + s)) * HH + h) * EE + e];
    g_Ek[i] = ex2f(kv * SCALE);
}

struct SmemT {
    union {
        float2 ek2[8 * SPAD2];               // one e-half as 8 interleaved pairs (32.9KB)
        struct {                             // overlaid once ek2 is dead:
            float probs[LT * SS];            // 16KB  (16B-aligned rows: SS*4=2048B)
            float part[4 * LT * DD];         // 8KB   (4 s-quarters)
            float rowsum[LT];
        } p2;
    } u;
    float eqrow[LT * EE];                    // Eq for this CTA's 8 rows
    float vm2[EE];                           // -2*v_e
    float klen[SS];
};

__global__ void __launch_bounds__(NT, 4)
addattn_main(const float* __restrict__ q,
             const float* __restrict__ vals, const float* __restrict__ vvec,
             const float* __restrict__ amask, const float* __restrict__ klen_g,
             float* __restrict__ out)
{
    __shared__ SmemT sm;

    const int tid  = threadIdx.x;
    const int wid  = tid >> 5;      // warp = L-row (0..7)
    const int lane = tid & 31;
    const int bid  = blockIdx.x;    // grid = 2*8*64 = 1024
    const int lt   = bid & 63;
    const int h    = (bid >> 6) & 7;
    const int b    = bid >> 9;
    const int l0   = lt * LT;

    const float* ekg = g_Ek + ((size_t)(b * HH + h) * EE) * SS;  // [e][s]

    // ---- stage: Eq rows (inline ex2), vm2, klen ----
    {
        int r = tid >> 5, e = tid & 31;   // 256 threads = 8 rows x 32 e
        float qv = q[(((size_t)(b * LL + l0 + r)) * HH + h) * EE + e];
        sm.eqrow[tid] = ex2f(qv * SCALE);
    }
    if (tid < EE) sm.vm2[tid] = -2.0f * vvec[tid];
    for (int s = tid; s < SS; s += NT) sm.klen[s] = klen_g[b * SS + s];

    // ---- stage Ek half-0 as interleaved pairs: ek2[ep][s] = (Ek[2ep][s], Ek[2ep+1][s]) ----
#pragma unroll
    for (int i = tid; i < 8 * 128; i += NT) {          // 8 pairs x 128 float4-chunks
        int ep = i >> 7, c = i & 127;
        float4 a4 = reinterpret_cast<const float4*>(ekg + (2 * ep)     * SS)[c];
        float4 b4 = reinterpret_cast<const float4*>(ekg + (2 * ep + 1) * SS)[c];
        float4* dst = reinterpret_cast<float4*>(&sm.u.ek2[ep * SPAD2 + c * 4]);
        dst[0] = make_float4(a4.x, b4.x, a4.y, b4.y);
        dst[1] = make_float4(a4.z, b4.z, a4.w, b4.w);
    }
    __syncthreads();

    float vsum = 0.f;
#pragma unroll
    for (int e = 0; e < EE; e++) vsum += sm.vm2[e];
    vsum *= -0.5f;                                 // sum_e v_e

    // ---- x init: score base + masks ----
    const float* amrow = amask + (size_t)(l0 + wid) * SS;
    float x[16];
#pragma unroll
    for (int j = 0; j < 16; j++) {
        int s = lane + 32 * j;
        x[j] = vsum + sm.klen[s] + amrow[s];
    }

    // ---- phase 1, e-half 0: 8 pairs, LDS.64 per pair, 1 RCP per 2 elements ----
    for (int ep = 0; ep < 8; ep++) {
        float eqa = sm.eqrow[wid * EE + 2 * ep];
        float eqb = sm.eqrow[wid * EE + 2 * ep + 1];
        float wa  = sm.vm2[2 * ep];
        float wb  = sm.vm2[2 * ep + 1];
        const float2* row = &sm.u.ek2[ep * SPAD2 + lane];
#pragma unroll
        for (int j0 = 0; j0 < 16; j0 += 8) {
            float num[8], den[8];
#pragma unroll
            for (int j = 0; j < 8; j++) {
                float2 ab = row[32 * (j0 + j)];
                float ta = fmaf(eqa, ab.x, 1.0f);
                float tb = fmaf(eqb, ab.y, 1.0f);
                den[j] = ta * tb;
                num[j] = fmaf(wb, ta, wa * tb);
            }
#pragma unroll
            for (int j = 0; j < 8; j++)
                x[j0 + j] = fmaf(num[j], rcpf(den[j]), x[j0 + j]);
        }
    }
    __syncthreads();
    // ---- stage half-1 (e in [16,32)) ----
#pragma unroll
    for (int i = tid; i < 8 * 128; i += NT) {
        int ep = i >> 7, c = i & 127;
        float4 a4 = reinterpret_cast<const float4*>(ekg + (16 + 2 * ep)     * SS)[c];
        float4 b4 = reinterpret_cast<const float4*>(ekg + (16 + 2 * ep + 1) * SS)[c];
        float4* dst = reinterpret_cast<float4*>(&sm.u.ek2[ep * SPAD2 + c * 4]);
        dst[0] = make_float4(a4.x, b4.x, a4.y, b4.y);
        dst[1] = make_float4(a4.z, b4.z, a4.w, b4.w);
    }
    __syncthreads();
    // ---- phase 1, e-half 1 ----
    for (int ep = 0; ep < 8; ep++) {
        float eqa = sm.eqrow[wid * EE + 16 + 2 * ep];
        float eqb = sm.eqrow[wid * EE + 16 + 2 * ep + 1];
        float wa  = sm.vm2[16 + 2 * ep];
        float wb  = sm.vm2[16 + 2 * ep + 1];
        const float2* row = &sm.u.ek2[ep * SPAD2 + lane];
#pragma unroll
        for (int j0 = 0; j0 < 16; j0 += 8) {
            float num[8], den[8];
#pragma unroll
            for (int j = 0; j < 8; j++) {
                float2 ab = row[32 * (j0 + j)];
                float ta = fmaf(eqa, ab.x, 1.0f);
                float tb = fmaf(eqb, ab.y, 1.0f);
                den[j] = ta * tb;
                num[j] = fmaf(wb, ta, wa * tb);
            }
#pragma unroll
            for (int j = 0; j < 8; j++)
                x[j0 + j] = fmaf(num[j], rcpf(den[j]), x[j0 + j]);
        }
    }
    __syncthreads();   // all warps done with ek2 before probs overlay

    // ---- phase 2: in-warp softmax (unnormalized) ----
    float m = -1e30f;
#pragma unroll
    for (int j = 0; j < 16; j++) m = fmaxf(m, x[j]);
#pragma unroll
    for (int o = 16; o > 0; o >>= 1)
        m = fmaxf(m, __shfl_xor_sync(0xffffffffu, m, o));
    float ssum = 0.f;
#pragma unroll
    for (int j = 0; j < 16; j++) {
        float p = ex2f((x[j] - m) * L2E);
        ssum += p;
        sm.u.p2.probs[wid * SS + lane + 32 * j] = p;
    }
#pragma unroll
    for (int o = 16; o > 0; o >>= 1)
        ssum += __shfl_xor_sync(0xffffffffu, ssum, o);
    if (lane == 0) sm.u.p2.rowsum[wid] = ssum;
    __syncthreads();

    // ---- phase 3: A @ V — 4 rows/warp x 4 s-quarters, probs via LDS.128 ----
    const int rg = wid & 1;          // row group: rows rg*4 .. rg*4+3
    const int sq = wid >> 1;         // s-quarter: [sq*128, sq*128+128)
    const int r0 = rg * 4;
    const int d0 = lane * 2;
    const float* vb = vals + ((size_t)(b * SS) * HH + h) * DD;
    float2 acc[4];
#pragma unroll
    for (int i = 0; i < 4; i++) acc[i] = make_float2(0.f, 0.f);

    const int sbeg = sq * 128;
#pragma unroll 2
    for (int s4 = sbeg; s4 < sbeg + 128; s4 += 4) {
        float4 p[4];
#pragma unroll
        for (int r = 0; r < 4; r++)
            p[r] = *reinterpret_cast<const float4*>(&sm.u.p2.probs[(r0 + r) * SS + s4]);
        float2 vv[4];
#pragma unroll
        for (int t = 0; t < 4; t++)
            vv[t] = *reinterpret_cast<const float2*>(vb + (size_t)(s4 + t) * (HH * DD) + d0);
#pragma unroll
        for (int r = 0; r < 4; r++) {
            acc[r].x = fmaf(p[r].x, vv[0].x, acc[r].x);
            acc[r].y = fmaf(p[r].x, vv[0].y, acc[r].y);
            acc[r].x = fmaf(p[r].y, vv[1].x, acc[r].x);
            acc[r].y = fmaf(p[r].y, vv[1].y, acc[r].y);
            acc[r].x = fmaf(p[r].z, vv[2].x, acc[r].x);
            acc[r].y = fmaf(p[r].z, vv[2].y, acc[r].y);
            acc[r].x = fmaf(p[r].w, vv[3].x, acc[r].x);
            acc[r].y = fmaf(p[r].w, vv[3].y, acc[r].y);
        }
    }
#pragma unroll
    for (int r = 0; r < 4; r++)
        *reinterpret_cast<float2*>(&sm.u.p2.part[(sq * LT + r0 + r) * DD + d0]) = acc[r];
    __syncthreads();

    // ---- combine 4 quarters, normalize, store ----
    for (int i = tid; i < LT * DD; i += NT) {
        int row = i >> 6, d = i & 63;
        float val = ((sm.u.p2.part[row * DD + d] + sm.u.p2.part[(LT + row) * DD + d]) +
                     (sm.u.p2.part[(2 * LT + row) * DD + d] + sm.u.p2.part[(3 * LT + row) * DD + d]))
                    * rcpf(sm.u.p2.rowsum[row]);
        out[(((size_t)(b * LL + l0 + row)) * HH + h) * DD + d] = val;
    }
}

extern "C" void kernel_launch(void* const* d_in, const int* in_sizes, int n_in,
                              void* d_out, int out_size)
{
    (void)in_sizes; (void)n_in; (void)out_size;
    const float* q     = (const float*)d_in[0];
    const float* k     = (const float*)d_in[1];
    const float* vals  = (const float*)d_in[2];
    const float* vvec  = (const float*)d_in[3];
    const float* amask = (const float*)d_in[4];
    const float* klen  = (const float*)d_in[5];

    prep_ek<<<(BB * HH * EE * SS) / 256, 256>>>(k);
    addattn_main<<<BB * HH * (LL / LT), NT>>>(q, vals, vvec, amask, klen,
                                              (float*)d_out);
}

// round 16
// speedup vs baseline: 1.5126x; 1.1101x over previous
#include <cuda_runtime.h>

// AdditiveAttention (Bahdanau): B=2, L=S=512, H=8, E=32, D=64
// score = sum_e v_e*tanh(q+k) + masks;  out = softmax_s @ values
// tanh: 1 - 2/(1+e^{2x}); e^{2(q+k)} = Eq*Ek (prep kernel).  Pairwise-exact:
//   wa/ta + wb/tb = (wa*tb+wb*ta)/(ta*tb),  t = 1 + Eq*Ek
// Phase-1 packed f32x2: each lane owns s-PAIRS; fma.rn.f32x2 does 2 FMAs/issue.

#define BB 2
#define LL 512
#define SS 512
#define HH 8
#define EE 32
#define DD 64
#define LT 8            // L-rows per CTA (one warp per row in phase 1)
#define NT 256
#define SPAD 516        // ek row stride in floats (rows 16B-aligned)
#define SCALE 2.8853900817779268f   /* 2*log2(e) */
#define L2E   1.4426950408889634f

typedef unsigned long long u64;

__device__ __forceinline__ float ex2f(float x) {
    float y; asm("ex2.approx.f32 %0, %1;" : "=f"(y) : "f"(x)); return y;
}
__device__ __forceinline__ float rcpf(float x) {
    float y; asm("rcp.approx.f32 %0, %1;" : "=f"(y) : "f"(x)); return y;
}
__device__ __forceinline__ u64 pk2(float lo, float hi) {
    u64 r;
    asm("mov.b64 %0, {%1, %2};" : "=l"(r)
        : "r"(__float_as_uint(lo)), "r"(__float_as_uint(hi)));
    return r;
}
__device__ __forceinline__ void up2(u64 v, float& lo, float& hi) {
    unsigned a, b;
    asm("mov.b64 {%0, %1}, %2;" : "=r"(a), "=r"(b) : "l"(v));
    lo = __uint_as_float(a); hi = __uint_as_float(b);
}
__device__ __forceinline__ u64 fma2(u64 a, u64 b, u64 c) {
    u64 d; asm("fma.rn.f32x2 %0, %1, %2, %3;" : "=l"(d) : "l"(a), "l"(b), "l"(c));
    return d;
}
__device__ __forceinline__ u64 mul2(u64 a, u64 b) {
    u64 d; asm("mul.rn.f32x2 %0, %1, %2;" : "=l"(d) : "l"(a), "l"(b));
    return d;
}
__device__ __forceinline__ u64 add2(u64 a, u64 b) {
    u64 d; asm("add.rn.f32x2 %0, %1, %2;" : "=l"(d) : "l"(a), "l"(b));
    return d;
}

__device__ float g_Ek[BB * HH * EE * SS];   // [b][h][e][s] = ex2(k*SCALE)

__global__ void prep_ek(const float* __restrict__ k) {
    int i = blockIdx.x * blockDim.x + threadIdx.x;   // 262144
    int s = i & (SS - 1);
    int e = (i >> 9) & (EE - 1);
    int h = (i >> 14) & (HH - 1);
    int b = i >> 17;
    float kv = k[(((size_t)(b * SS + s)) * HH + h) * EE + e];
    g_Ek[i] = ex2f(kv * SCALE);
}

struct SmemT {
    union {
        float ek[16 * SPAD];                 // one e-half, plain [e][s] rows (33KB)
        struct {                             // overlaid once ek is dead:
            float probs[LT * SS];            // 16KB
            float part[4 * LT * DD];         // 8KB (4 s-quarters)
            float rowsum[LT];
        } p2;
    } u;
    float eqrow[LT * EE];                    // Eq for this CTA's 8 rows
    float vm2[EE];                           // -2*v_e
    float klen[SS];
};

__global__ void __launch_bounds__(NT, 4)
addattn_main(const float* __restrict__ q,
             const float* __restrict__ vals, const float* __restrict__ vvec,
             const float* __restrict__ amask, const float* __restrict__ klen_g,
             float* __restrict__ out)
{
    __shared__ SmemT sm;

    const int tid  = threadIdx.x;
    const int wid  = tid >> 5;      // warp = L-row (0..7)
    const int lane = tid & 31;
    const int bid  = blockIdx.x;    // grid = 2*8*64 = 1024
    const int lt   = bid & 63;
    const int h    = (bid >> 6) & 7;
    const int b    = bid >> 9;
    const int l0   = lt * LT;

    const float* ekg = g_Ek + ((size_t)(b * HH + h) * EE) * SS;  // [e][s]

    // ---- stage: Eq rows (inline ex2), vm2, klen ----
    {
        int r = tid >> 5, e = tid & 31;
        float qv = q[(((size_t)(b * LL + l0 + r)) * HH + h) * EE + e];
        sm.eqrow[tid] = ex2f(qv * SCALE);
    }
    if (tid < EE) sm.vm2[tid] = -2.0f * vvec[tid];
    for (int s = tid; s < SS; s += NT) sm.klen[s] = klen_g[b * SS + s];

    // ---- stage Ek half-0, plain rows ----
#pragma unroll
    for (int i = tid; i < (16 * SS) / 4; i += NT) {
        float4 v4 = reinterpret_cast<const float4*>(ekg)[i];
        int e = i >> 7, c = i & 127;
        *reinterpret_cast<float4*>(&sm.u.ek[e * SPAD + c * 4]) = v4;
    }
    __syncthreads();

    float vsum = 0.f;
#pragma unroll
    for (int e = 0; e < EE; e++) vsum += sm.vm2[e];
    vsum *= -0.5f;                                 // sum_e v_e

    // ---- x2 init: lane owns s-pairs s = 2*lane + 64*jj (+0/+1) ----
    const u64* am64 = reinterpret_cast<const u64*>(amask + (size_t)(l0 + wid) * SS);
    const u64* kl64 = reinterpret_cast<const u64*>(sm.klen);
    const u64 ONE2  = pk2(1.0f, 1.0f);
    const u64 vs2   = pk2(vsum, vsum);
    u64 x2[8];
#pragma unroll
    for (int jj = 0; jj < 8; jj++)
        x2[jj] = add2(vs2, add2(am64[lane + 32 * jj], kl64[lane + 32 * jj]));

    // ---- phase 1, e-half 0: packed f32x2, 1 RCP per element-pair ----
    for (int ep = 0; ep < 8; ep++) {
        float eqa = sm.eqrow[wid * EE + 2 * ep];
        float eqb = sm.eqrow[wid * EE + 2 * ep + 1];
        u64 eqa2 = pk2(eqa, eqa), eqb2 = pk2(eqb, eqb);
        float wa = sm.vm2[2 * ep], wb = sm.vm2[2 * ep + 1];
        u64 wa2 = pk2(wa, wa), wb2 = pk2(wb, wb);
        const u64* rowa = reinterpret_cast<const u64*>(&sm.u.ek[(2 * ep)     * SPAD]);
        const u64* rowb = reinterpret_cast<const u64*>(&sm.u.ek[(2 * ep + 1) * SPAD]);
#pragma unroll
        for (int jjb = 0; jjb < 8; jjb += 4) {
            u64 num2[4]; float dl[4], dh[4];
#pragma unroll
            for (int t = 0; t < 4; t++) {
                int jj = jjb + t;
                u64 ta2 = fma2(eqa2, rowa[lane + 32 * jj], ONE2);
                u64 tb2 = fma2(eqb2, rowb[lane + 32 * jj], ONE2);
                up2(mul2(ta2, tb2), dl[t], dh[t]);
                num2[t] = fma2(wb2, ta2, mul2(wa2, tb2));
            }
#pragma unroll
            for (int t = 0; t < 4; t++) {
                u64 r2 = pk2(rcpf(dl[t]), rcpf(dh[t]));
                x2[jjb + t] = fma2(num2[t], r2, x2[jjb + t]);
            }
        }
    }
    __syncthreads();
    // ---- stage half-1 (e in [16,32)) ----
#pragma unroll
    for (int i = tid; i < (16 * SS) / 4; i += NT) {
        float4 v4 = reinterpret_cast<const float4*>(ekg + 16 * SS)[i];
        int e = i >> 7, c = i & 127;
        *reinterpret_cast<float4*>(&sm.u.ek[e * SPAD + c * 4]) = v4;
    }
    __syncthreads();
    // ---- phase 1, e-half 1 ----
    for (int ep = 0; ep < 8; ep++) {
        float eqa = sm.eqrow[wid * EE + 16 + 2 * ep];
        float eqb = sm.eqrow[wid * EE + 16 + 2 * ep + 1];
        u64 eqa2 = pk2(eqa, eqa), eqb2 = pk2(eqb, eqb);
        float wa = sm.vm2[16 + 2 * ep], wb = sm.vm2[16 + 2 * ep + 1];
        u64 wa2 = pk2(wa, wa), wb2 = pk2(wb, wb);
        const u64* rowa = reinterpret_cast<const u64*>(&sm.u.ek[(2 * ep)     * SPAD]);
        const u64* rowb = reinterpret_cast<const u64*>(&sm.u.ek[(2 * ep + 1) * SPAD]);
#pragma unroll
        for (int jjb = 0; jjb < 8; jjb += 4) {
            u64 num2[4]; float dl[4], dh[4];
#pragma unroll
            for (int t = 0; t < 4; t++) {
                int jj = jjb + t;
                u64 ta2 = fma2(eqa2, rowa[lane + 32 * jj], ONE2);
                u64 tb2 = fma2(eqb2, rowb[lane + 32 * jj], ONE2);
                up2(mul2(ta2, tb2), dl[t], dh[t]);
                num2[t] = fma2(wb2, ta2, mul2(wa2, tb2));
            }
#pragma unroll
            for (int t = 0; t < 4; t++) {
                u64 r2 = pk2(rcpf(dl[t]), rcpf(dh[t]));
                x2[jjb + t] = fma2(num2[t], r2, x2[jjb + t]);
            }
        }
    }
    __syncthreads();   // all warps done with ek before probs overlay

    // ---- phase 2: in-warp softmax (unnormalized) ----
    float x[16];
#pragma unroll
    for (int jj = 0; jj < 8; jj++) up2(x2[jj], x[2 * jj], x[2 * jj + 1]);
    float m = -1e30f;
#pragma unroll
    for (int j = 0; j < 16; j++) m = fmaxf(m, x[j]);
#pragma unroll
    for (int o = 16; o > 0; o >>= 1)
        m = fmaxf(m, __shfl_xor_sync(0xffffffffu, m, o));
    float ssum = 0.f;
    u64* pr64 = reinterpret_cast<u64*>(&sm.u.p2.probs[wid * SS]);
#pragma unroll
    for (int jj = 0; jj < 8; jj++) {
        float p0 = ex2f((x[2 * jj] - m) * L2E);
        float p1 = ex2f((x[2 * jj + 1] - m) * L2E);
        ssum += p0 + p1;
        pr64[lane + 32 * jj] = pk2(p0, p1);     // s = 2*lane + 64*jj
    }
#pragma unroll
    for (int o = 16; o > 0; o >>= 1)
        ssum += __shfl_xor_sync(0xffffffffu, ssum, o);
    if (lane == 0) sm.u.p2.rowsum[wid] = ssum;
    __syncthreads();

    // ---- phase 3: A @ V — 4 rows/warp x 4 s-quarters, probs via LDS.128 ----
    const int rg = wid & 1;          // row group: rows rg*4 .. rg*4+3
    const int sq = wid >> 1;         // s-quarter
    const int r0 = rg * 4;
    const int d0 = lane * 2;
    const float* vb = vals + ((size_t)(b * SS) * HH + h) * DD;
    float2 acc[4];
#pragma unroll
    for (int i = 0; i < 4; i++) acc[i] = make_float2(0.f, 0.f);

    const int sbeg = sq * 128;
#pragma unroll 2
    for (int s4 = sbeg; s4 < sbeg + 128; s4 += 4) {
        float4 p[4];
#pragma unroll
        for (int r = 0; r < 4; r++)
            p[r] = *reinterpret_cast<const float4*>(&sm.u.p2.probs[(r0 + r) * SS + s4]);
        float2 vv[4];
#pragma unroll
        for (int t = 0; t < 4; t++)
            vv[t] = *reinterpret_cast<const float2*>(vb + (size_t)(s4 + t) * (HH * DD) + d0);
#pragma unroll
        for (int r = 0; r < 4; r++) {
            acc[r].x = fmaf(p[r].x, vv[0].x, acc[r].x);
            acc[r].y = fmaf(p[r].x, vv[0].y, acc[r].y);
            acc[r].x = fmaf(p[r].y, vv[1].x, acc[r].x);
            acc[r].y = fmaf(p[r].y, vv[1].y, acc[r].y);
            acc[r].x = fmaf(p[r].z, vv[2].x, acc[r].x);
            acc[r].y = fmaf(p[r].z, vv[2].y, acc[r].y);
            acc[r].x = fmaf(p[r].w, vv[3].x, acc[r].x);
            acc[r].y = fmaf(p[r].w, vv[3].y, acc[r].y);
        }
    }
#pragma unroll
    for (int r = 0; r < 4; r++)
        *reinterpret_cast<float2*>(&sm.u.p2.part[(sq * LT + r0 + r) * DD + d0]) = acc[r];
    __syncthreads();

    // ---- combine 4 quarters, normalize, store ----
    for (int i = tid; i < LT * DD; i += NT) {
        int row = i >> 6, d = i & 63;
        float val = ((sm.u.p2.part[row * DD + d] + sm.u.p2.part[(LT + row) * DD + d]) +
                     (sm.u.p2.part[(2 * LT + row) * DD + d] + sm.u.p2.part[(3 * LT + row) * DD + d]))
                    * rcpf(sm.u.p2.rowsum[row]);
        out[(((size_t)(b * LL + l0 + row)) * HH + h) * DD + d] = val;
    }
}

extern "C" void kernel_launch(void* const* d_in, const int* in_sizes, int n_in,
                              void* d_out, int out_size)
{
    (void)in_sizes; (void)n_in; (void)out_size;
    const float* q     = (const float*)d_in[0];
    const float* k     = (const float*)d_in[1];
    const float* vals  = (const float*)d_in[2];
    const float* vvec  = (const float*)d_in[3];
    const float* amask = (const float*)d_in[4];
    const float* klen  = (const float*)d_in[5];

    prep_ek<<<(BB * HH * EE * SS) / 256, 256>>>(k);
    addattn_main<<<BB * HH * (LL / LT), NT>>>(q, vals, vvec, amask, klen,
                                              (float*)d_out);
}